// round 9
// baseline (speedup 1.0000x reference)
#include <cuda_runtime.h>
#include <math.h>
#include <stdint.h>

// Problem constants (fixed by reference setup_inputs)
#define BB    512
#define KK    8
#define PP    6
#define DD    1024
#define NIDS  64
#define NGRP  (2 * NIDS)
#define MARGIN 0.2f
#define ROW4  (DD / 4)            // 256 float4 per D-row

// Scratch (no allocations allowed)
__device__ float g_w[BB];
__device__ float g_cinv[BB];
__device__ int   g_boff[BB];
__device__ int   g_bcnt[BB];
__device__ int   g_list[BB];

// ---------------------------------------------------------------------------
// K1: one block, 512 threads. Counts, validity, id_count, fused weights,
//     per-sample cross-group CSR (offset,count), zero d_out.
// ---------------------------------------------------------------------------
__global__ void k1_setup(const int* __restrict__ pids,
                         const int* __restrict__ camids,
                         float* __restrict__ out) {
    __shared__ int scnt[NGRP];
    __shared__ int scur[NGRP];
    __shared__ int soff[NGRP + 1];
    __shared__ int svalid[NIDS];
    __shared__ int s_idcount;

    int t = threadIdx.x;
    if (t < NGRP) { scnt[t] = 0; scur[t] = 0; }
    if (t == 0) s_idcount = 0;
    __syncthreads();

    int pid = 0, cam = 0, own_grp = 0;
    if (t < BB) {
        pid = pids[t];
        cam = camids[t];
        int mod = (cam == 0) ? 0 : 1;
        own_grp = mod * NIDS + pid;
        atomicAdd(&scnt[own_grp], 1);
    }
    __syncthreads();

    if (t < NIDS) {
        int v = (scnt[t] > 0 && scnt[NIDS + t] > 0) ? 1 : 0;
        svalid[t] = v;
        if (v) atomicAdd(&s_idcount, 1);
    }
    __syncthreads();

    if (t == 0) {
        int acc = 0;
        for (int g = 0; g < NGRP; ++g) { soff[g] = acc; acc += scnt[g]; }
        soff[NGRP] = acc;
    }
    __syncthreads();

    float denom = fmaxf((float)s_idcount, 1.0f);

    if (t < BB) {
        int rgb = (cam == 0);
        int cross_grp = (rgb ? 1 : 0) * NIDS + pid;
        float grp_cnt = fmaxf((float)scnt[own_grp], 1.0f);
        float w = svalid[pid] ? (1.0f / (grp_cnt * (float)KK * (float)PP * denom)) : 0.0f;
        g_w[t] = w;
        g_cinv[t] = 1.0f / fmaxf((float)scnt[cross_grp], 1.0f);
        g_boff[t] = soff[cross_grp];
        g_bcnt[t] = scnt[cross_grp];
        int pos = atomicAdd(&scur[own_grp], 1);
        g_list[soff[own_grp] + pos] = t;
    }
    if (t == 0) out[0] = 0.0f;
}

// --- cp.async helpers ------------------------------------------------------
__device__ __forceinline__ void cp16(uint32_t saddr, const void* gaddr) {
    asm volatile("cp.async.cg.shared.global [%0], [%1], 16;\n"
                 :: "r"(saddr), "l"(gaddr));
}
__device__ __forceinline__ void cp_commit() {
    asm volatile("cp.async.commit_group;\n");
}
template <int N>
__device__ __forceinline__ void cp_wait() {
    asm volatile("cp.async.wait_group %0;\n" :: "n"(N));
}

// ---------------------------------------------------------------------------
// K4: one block per (b,p). All 8 k-rows of f_gen prefetched via cp.async at
//     entry (zero register cost); center/own gathered to registers while the
//     copies fly; no barrier in the row loop (thread-private ring slots).
// ---------------------------------------------------------------------------
__global__ void __launch_bounds__(256, 6) k4_main(const float* __restrict__ f_orig,
                                                  const float* __restrict__ f_gen,
                                                  float* __restrict__ out) {
    __shared__ float4 ring[KK][256];       // 32 KB: one slot per k-row
    __shared__ float  sred[KK][8][2];      // per-row per-warp (pull, push)

    int bp = blockIdx.x;                   // 0 .. BB*PP-1
    int b = bp / PP;
    int p = bp - b * PP;
    int t = threadIdx.x;
    int w = t >> 5;
    int lane = t & 31;

    // --- 1. Launch all 8 row prefetches (one 16B cp.async per thread/row) ---
    const float* grow0 = f_gen + ((size_t)(b * KK) * PP + p) * DD + t * 4;
    uint32_t sbase = (uint32_t)__cvta_generic_to_shared(&ring[0][t]);
#pragma unroll
    for (int r = 0; r < KK; ++r) {
        cp16(sbase + r * (256 * 16), grow0 + r * (PP * DD));
        cp_commit();
    }

    // --- 2. Prologue to registers (overlaps with prefetch flight) ---
    const float4* fo4 = reinterpret_cast<const float4*>(f_orig);
    size_t orow = ((size_t)(b * PP + p) * DD) >> 2;
    float4 o4 = fo4[orow + t];

    int off = g_boff[b];
    int cnt = g_bcnt[b];
    float cinv = g_cinv[b];
    float4 c4 = make_float4(0.f, 0.f, 0.f, 0.f);
    for (int j = 0; j < cnt; ++j) {
        int bs = g_list[off + j];
        float4 v = fo4[(((size_t)(bs * PP + p) * DD) >> 2) + t];
        c4.x += v.x; c4.y += v.y; c4.z += v.z; c4.w += v.w;
    }
    c4.x *= cinv; c4.y *= cinv; c4.z *= cinv; c4.w *= cinv;

    // --- 3. Row loop: wait -> LDS -> compute -> warp reduce -> store pair ---
#define DO_ROW(R)                                                              \
    {                                                                          \
        cp_wait<KK - 1 - (R)>();                                               \
        float4 g = ring[R][t];                                                 \
        float dx, dy, dz, dw;                                                  \
        dx = g.x - c4.x; dy = g.y - c4.y; dz = g.z - c4.z; dw = g.w - c4.w;    \
        float s_pull = dx * dx + dy * dy + dz * dz + dw * dw;                  \
        dx = g.x - o4.x; dy = g.y - o4.y; dz = g.z - o4.z; dw = g.w - o4.w;    \
        float s_push = dx * dx + dy * dy + dz * dz + dw * dw;                  \
        for (int s = 16; s; s >>= 1) {                                         \
            s_pull += __shfl_down_sync(0xffffffffu, s_pull, s);                \
            s_push += __shfl_down_sync(0xffffffffu, s_push, s);                \
        }                                                                      \
        if (lane == 0) { sred[R][w][0] = s_pull; sred[R][w][1] = s_push; }     \
    }
    DO_ROW(0) DO_ROW(1) DO_ROW(2) DO_ROW(3)
    DO_ROW(4) DO_ROW(5) DO_ROW(6) DO_ROW(7)
#undef DO_ROW

    // --- 4. Tail: fold 8 rows x 8 warps, hinge, one atomic ---
    __syncthreads();
    if (w == 0) {
        float h = 0.0f;
        if (lane < KK) {
            float pl = 0.f, ps = 0.f;
#pragma unroll
            for (int i = 0; i < 8; ++i) { pl += sred[lane][i][0]; ps += sred[lane][i][1]; }
            h = fmaxf(sqrtf(pl) - sqrtf(ps) + MARGIN, 0.0f);
        }
#pragma unroll
        for (int s = 4; s; s >>= 1) h += __shfl_down_sync(0xffffffffu, h, s);
        if (lane == 0) atomicAdd(out, h * g_w[b]);
    }
}

// ---------------------------------------------------------------------------
extern "C" void kernel_launch(void* const* d_in, const int* in_sizes, int n_in,
                              void* d_out, int out_size) {
    const float* f_orig = (const float*)d_in[0];
    const float* f_gen  = (const float*)d_in[1];
    const int*   pids   = (const int*)d_in[2];
    const int*   camids = (const int*)d_in[3];
    float*       out    = (float*)d_out;

    k1_setup<<<1, 512>>>(pids, camids, out);
    k4_main<<<BB * PP, 256>>>(f_orig, f_gen, out);
}

// round 10
// speedup vs baseline: 1.1988x; 1.1988x over previous
#include <cuda_runtime.h>
#include <math.h>

// Problem constants (fixed by reference setup_inputs)
#define BB    512
#define KK    8
#define PP    6
#define DD    1024
#define NIDS  64
#define MARGIN 0.2f
#define ROW4  (DD / 4)            // 256 float4 per D-row
#define GRID  (BB * PP)           // 3072 blocks

// Cross-call accumulator state (statically zero-initialized; each call
// resets it in the last-block epilogue, so graph replays are deterministic).
__device__ float        g_accum = 0.0f;
__device__ unsigned int g_done  = 0u;

// ---------------------------------------------------------------------------
// Fused kernel: one block per (b,p).
//   Phase A (setup, ~few hundred cycles): local 2x64 histogram of
//     (modality,pid) from pids/camids, validity + id_count, own/cross counts,
//     cross-group member list for sample b.
//   Phase B (prologue): stage own f_original row + gathered cross-center row
//     in SMEM.
//   Phase C (main, R4 shape): warp k streams f_generated[b,k,p,:] with 8
//     batched float4 loads vs the SMEM rows; hinge; block partial.
//   Phase D (epilogue): atomicAdd to g_accum; last finished block writes
//     d_out and resets the accumulator state.
// ---------------------------------------------------------------------------
__global__ void __launch_bounds__(256) cpm_fused(const float* __restrict__ f_orig,
                                                 const float* __restrict__ f_gen,
                                                 const int*   __restrict__ pids,
                                                 const int*   __restrict__ camids,
                                                 float*       __restrict__ out) {
    __shared__ float so[DD];              // own f_original row      (4 KB)
    __shared__ float sc[DD];              // cross-center row        (4 KB)
    __shared__ int   scnt[2 * NIDS];      // (mod,id) histogram
    __shared__ int   slist[BB];           // cross-group members     (2 KB)
    __shared__ int   snm;                 // cross-group count
    __shared__ int   sidc;                // id_count
    __shared__ float sw;                  // fused weight for sample b
    __shared__ float scinv;               // 1/max(cnt_cross,1)
    __shared__ float spart[8];

    int bp = blockIdx.x;                  // 0 .. GRID-1
    int b = bp / PP;
    int p = bp - b * PP;
    int t = threadIdx.x;                  // 256 threads
    int w = t >> 5;
    int lane = t & 31;

    // ---- Phase A: local setup -------------------------------------------
    if (t < 2 * NIDS) scnt[t] = 0;
    if (t == 0) { snm = 0; sidc = 0; }
    __syncthreads();

    int pid_b = pids[b];
    int cam_b = camids[b];
    int cross_mod = (cam_b == 0) ? 1 : 0;

#pragma unroll
    for (int i = t; i < BB; i += 256) {
        int pid = pids[i];
        int mod = (camids[i] == 0) ? 0 : 1;
        atomicAdd(&scnt[mod * NIDS + pid], 1);
        if (pid == pid_b && mod == cross_mod) {
            int pos = atomicAdd(&snm, 1);
            slist[pos] = i;
        }
    }
    __syncthreads();

    if (t < NIDS) {
        if (scnt[t] > 0 && scnt[NIDS + t] > 0) atomicAdd(&sidc, 1);
    }
    __syncthreads();

    if (t == 0) {
        int own_mod = cross_mod ^ 1;
        int own_cnt = scnt[own_mod * NIDS + pid_b];
        int valid = (scnt[pid_b] > 0 && scnt[NIDS + pid_b] > 0);
        float denom = fmaxf((float)sidc, 1.0f);
        sw = valid ? (1.0f / (fmaxf((float)own_cnt, 1.0f) *
                              (float)KK * (float)PP * denom)) : 0.0f;
        scinv = 1.0f / fmaxf((float)snm, 1.0f);
    }
    __syncthreads();

    // ---- Phase B: prologue ----------------------------------------------
    const float4* fo4 = reinterpret_cast<const float4*>(f_orig);
    float4* so4 = reinterpret_cast<float4*>(so);
    float4* sc4 = reinterpret_cast<float4*>(sc);

    so4[t] = fo4[(((size_t)(b * PP + p) * DD) >> 2) + t];

    int cnt = snm;
    float cinv = scinv;
    float4 acc = make_float4(0.f, 0.f, 0.f, 0.f);
    int j = 0;
    for (; j + 4 <= cnt; j += 4) {
        int b0 = slist[j + 0], b1 = slist[j + 1];
        int b2 = slist[j + 2], b3 = slist[j + 3];
        float4 v0 = fo4[(((size_t)(b0 * PP + p) * DD) >> 2) + t];
        float4 v1 = fo4[(((size_t)(b1 * PP + p) * DD) >> 2) + t];
        float4 v2 = fo4[(((size_t)(b2 * PP + p) * DD) >> 2) + t];
        float4 v3 = fo4[(((size_t)(b3 * PP + p) * DD) >> 2) + t];
        acc.x += (v0.x + v1.x) + (v2.x + v3.x);
        acc.y += (v0.y + v1.y) + (v2.y + v3.y);
        acc.z += (v0.z + v1.z) + (v2.z + v3.z);
        acc.w += (v0.w + v1.w) + (v2.w + v3.w);
    }
    for (; j < cnt; ++j) {
        int bs = slist[j];
        float4 v = fo4[(((size_t)(bs * PP + p) * DD) >> 2) + t];
        acc.x += v.x; acc.y += v.y; acc.z += v.z; acc.w += v.w;
    }
    acc.x *= cinv; acc.y *= cinv; acc.z *= cinv; acc.w *= cinv;
    sc4[t] = acc;
    __syncthreads();

    // ---- Phase C: main stream (R4 shape) --------------------------------
    const float4* gp = reinterpret_cast<const float4*>(
        f_gen + ((size_t)((b * KK + w) * PP + p)) * DD);

    float4 g[8];
#pragma unroll
    for (int it = 0; it < 8; ++it) g[it] = gp[it * 32 + lane];

    float s_pull = 0.0f, s_push = 0.0f;
#pragma unroll
    for (int it = 0; it < 8; ++it) {
        float4 o = so4[it * 32 + lane];
        float4 c = sc4[it * 32 + lane];
        float dx, dy, dz, dw;
        dx = g[it].x - c.x; dy = g[it].y - c.y;
        dz = g[it].z - c.z; dw = g[it].w - c.w;
        s_pull += dx * dx + dy * dy + dz * dz + dw * dw;
        dx = g[it].x - o.x; dy = g[it].y - o.y;
        dz = g[it].z - o.z; dw = g[it].w - o.w;
        s_push += dx * dx + dy * dy + dz * dz + dw * dw;
    }
#pragma unroll
    for (int s = 16; s; s >>= 1) {
        s_pull += __shfl_down_sync(0xffffffffu, s_pull, s);
        s_push += __shfl_down_sync(0xffffffffu, s_push, s);
    }
    if (lane == 0) {
        float h = sqrtf(s_pull) - sqrtf(s_push) + MARGIN;
        spart[w] = fmaxf(h, 0.0f);
    }
    __syncthreads();

    // ---- Phase D: epilogue ----------------------------------------------
    if (t == 0) {
        float s = 0.0f;
#pragma unroll
        for (int i = 0; i < 8; ++i) s += spart[i];
        atomicAdd(&g_accum, s * sw);
        __threadfence();
        unsigned r = atomicAdd(&g_done, 1u);
        if (r == (unsigned)(GRID - 1)) {          // last block to finish
            float v = atomicExch(&g_accum, 0.0f); // read + reset for replay
            out[0] = v;
            g_done = 0u;
        }
    }
}

// ---------------------------------------------------------------------------
extern "C" void kernel_launch(void* const* d_in, const int* in_sizes, int n_in,
                              void* d_out, int out_size) {
    const float* f_orig = (const float*)d_in[0];
    const float* f_gen  = (const float*)d_in[1];
    const int*   pids   = (const int*)d_in[2];
    const int*   camids = (const int*)d_in[3];
    float*       out    = (float*)d_out;

    cpm_fused<<<GRID, 256>>>(f_orig, f_gen, pids, camids, out);
}